// round 2
// baseline (speedup 1.0000x reference)
#include <cuda_runtime.h>

// ---------------------------------------------------------------------------
// Criss-cross attention block, fp32 staged pipeline.
// B=8, C=256, CQ=32, H=W=128.
// ---------------------------------------------------------------------------

#define Bn 8
#define Cc 256
#define CQn 32
#define Hh 128
#define Wn 128
#define HWn (Hh*Wn)

// Scratch (static device arrays; no runtime allocation).
__device__ float g_q_hw[Bn*HWn*CQn];       // [b][h][w][o]
__device__ float g_q_wh[Bn*HWn*CQn];       // [b][w][h][o]
__device__ float g_k_hw[Bn*HWn*CQn];       // [b][h][w][o]
__device__ float g_k_wh[Bn*HWn*CQn];       // [b][w][h][o]
__device__ float g_v_hwc[Bn*HWn*Cc];       // [b][h][w][c]
__device__ float g_v_whc[Bn*HWn*Cc];       // [b][w][h][c]
__device__ float g_eH[Bn*Wn*Hh*Hh];        // [b][w][h][g]   (g over H)
__device__ float g_eW[Bn*Hh*Wn*Wn];        // [b][h][w][g]   (g over W)
__device__ float g_oH[Bn*HWn*Cc];          // [b][w][h][c]
__device__ float g_oW[Bn*HWn*Cc];          // [b][h][w][c]

__device__ __forceinline__ float neg_inf_f() { return __int_as_float(0xff800000); }

// ---------------------------------------------------------------------------
// Kernel 1: fused QKV projection.
// Out(320 x 16384) = [Wq;Wk;Wv](320x256) @ X_b(256x16384) + bias.
// grid: (256 n-tiles, 5 m-tiles, B), block 256, 64x64 tile, 4x4 per thread.
// ---------------------------------------------------------------------------
__global__ __launch_bounds__(256) void proj_kernel(
    const float* __restrict__ x,
    const float* __restrict__ Wq, const float* __restrict__ bq,
    const float* __restrict__ Wk, const float* __restrict__ bk,
    const float* __restrict__ Wv, const float* __restrict__ bv)
{
    __shared__ float As[16][64];   // As[k][m]
    __shared__ float Bs[16][64];   // Bs[k][n]

    const int b  = blockIdx.z;
    const int mt = blockIdx.y;
    const int n0 = blockIdx.x * 64;
    const int t  = threadIdx.x;
    const int tx = t & 15, ty = t >> 4;

    // A loader: thread loads one float4 per k-chunk from its assigned row.
    const int arow = t >> 2;         // 0..63
    const int afq  = (t & 3) * 4;    // 0,4,8,12
    const int r    = mt * 64 + arow; // global output row in [0,320)
    const float* Arow;
    if      (r < 32) Arow = Wq + r * Cc;
    else if (r < 64) Arow = Wk + (r - 32) * Cc;
    else             Arow = Wv + (r - 64) * Cc;

    // B loader
    const int bkk = t >> 4;          // 0..15
    const int bnq = (t & 15) * 4;
    const float* Xb = x + (size_t)b * Cc * HWn;

    float acc[4][4];
    #pragma unroll
    for (int i = 0; i < 4; i++)
        #pragma unroll
        for (int j = 0; j < 4; j++) acc[i][j] = 0.f;

    for (int kc = 0; kc < Cc; kc += 16) {
        float4 av = *reinterpret_cast<const float4*>(Arow + kc + afq);
        float4 xv = *reinterpret_cast<const float4*>(Xb + (size_t)(kc + bkk) * HWn + n0 + bnq);
        __syncthreads();
        As[afq + 0][arow] = av.x;
        As[afq + 1][arow] = av.y;
        As[afq + 2][arow] = av.z;
        As[afq + 3][arow] = av.w;
        *reinterpret_cast<float4*>(&Bs[bkk][bnq]) = xv;
        __syncthreads();
        #pragma unroll
        for (int kk = 0; kk < 16; kk++) {
            float a0 = As[kk][ty * 4 + 0];
            float a1 = As[kk][ty * 4 + 1];
            float a2 = As[kk][ty * 4 + 2];
            float a3 = As[kk][ty * 4 + 3];
            float4 bb = *reinterpret_cast<float4*>(&Bs[kk][tx * 4]);
            acc[0][0] += a0 * bb.x; acc[0][1] += a0 * bb.y; acc[0][2] += a0 * bb.z; acc[0][3] += a0 * bb.w;
            acc[1][0] += a1 * bb.x; acc[1][1] += a1 * bb.y; acc[1][2] += a1 * bb.z; acc[1][3] += a1 * bb.w;
            acc[2][0] += a2 * bb.x; acc[2][1] += a2 * bb.y; acc[2][2] += a2 * bb.z; acc[2][3] += a2 * bb.w;
            acc[3][0] += a3 * bb.x; acc[3][1] += a3 * bb.y; acc[3][2] += a3 * bb.z; acc[3][3] += a3 * bb.w;
        }
    }

    // Epilogue: bias + scatter into channel-last dual layouts.
    #pragma unroll
    for (int i = 0; i < 4; i++) {
        const int rr = mt * 64 + ty * 4 + i;
        int o; float bias; int which;   // 0=q,1=k,2=v
        if (rr < 32)      { o = rr;      bias = bq[o]; which = 0; }
        else if (rr < 64) { o = rr - 32; bias = bk[o]; which = 1; }
        else              { o = rr - 64; bias = bv[o]; which = 2; }
        #pragma unroll
        for (int j = 0; j < 4; j++) {
            const int p = n0 + tx * 4 + j;
            const int h = p >> 7, w = p & 127;
            const float val = acc[i][j] + bias;
            const size_t idx_hw = (size_t)(b * Hh + h) * Wn + w;
            const size_t idx_wh = (size_t)(b * Wn + w) * Hh + h;
            if (which == 0)      { g_q_hw[idx_hw * CQn + o] = val; g_q_wh[idx_wh * CQn + o] = val; }
            else if (which == 1) { g_k_hw[idx_hw * CQn + o] = val; g_k_wh[idx_wh * CQn + o] = val; }
            else                 { g_v_hwc[idx_hw * Cc + o] = val; g_v_whc[idx_wh * Cc + o] = val; }
        }
    }
}

// ---------------------------------------------------------------------------
// Kernel 2/3: score GEMMs. 128x128x32 per block.
// ISH=true : per (b,w): eH[h][g] = Q_wh(h,:) . K_wh(g,:)   (diag h==g -> -inf)
// ISH=false: per (b,h): eW[w][g] = Q_hw(w,:) . K_hw(g,:)
// grid: B*128 blocks, block 256 threads, 8x8 per thread.
// ---------------------------------------------------------------------------
template <bool ISH>
__global__ __launch_bounds__(256) void score_kernel()
{
    __shared__ float Qs[128][32];
    __shared__ float Ks[32][132];   // transposed, padded

    const int bs = blockIdx.x;      // b*128 + (w or h)
    const int t  = threadIdx.x;
    const float* Q = (ISH ? g_q_wh : g_q_hw) + (size_t)bs * 128 * CQn;
    const float* K = (ISH ? g_k_wh : g_k_hw) + (size_t)bs * 128 * CQn;
    float* O       = (ISH ? g_eH   : g_eW)   + (size_t)bs * 128 * 128;

    #pragma unroll
    for (int q = 0; q < 4; q++) {
        const int idx = q * 256 + t;        // 0..1023 float4 slots
        const int row = idx >> 3;           // 0..127
        const int oq  = (idx & 7) * 4;      // 0..28
        float4 qv = *reinterpret_cast<const float4*>(Q + row * CQn + oq);
        *reinterpret_cast<float4*>(&Qs[row][oq]) = qv;
        float4 kv = *reinterpret_cast<const float4*>(K + row * CQn + oq);
        Ks[oq + 0][row] = kv.x;
        Ks[oq + 1][row] = kv.y;
        Ks[oq + 2][row] = kv.z;
        Ks[oq + 3][row] = kv.w;
    }
    __syncthreads();

    const int tx = t & 15, ty = t >> 4;
    const int h0 = ty * 8, g0 = tx * 8;
    float acc[8][8];
    #pragma unroll
    for (int i = 0; i < 8; i++)
        #pragma unroll
        for (int j = 0; j < 8; j++) acc[i][j] = 0.f;

    #pragma unroll
    for (int o = 0; o < 32; o++) {
        float a[8];
        #pragma unroll
        for (int i = 0; i < 8; i++) a[i] = Qs[h0 + i][o];
        float4 b0 = *reinterpret_cast<float4*>(&Ks[o][g0]);
        float4 b1 = *reinterpret_cast<float4*>(&Ks[o][g0 + 4]);
        float bb[8] = {b0.x, b0.y, b0.z, b0.w, b1.x, b1.y, b1.z, b1.w};
        #pragma unroll
        for (int i = 0; i < 8; i++)
            #pragma unroll
            for (int j = 0; j < 8; j++)
                acc[i][j] += a[i] * bb[j];
    }

    #pragma unroll
    for (int i = 0; i < 8; i++) {
        const int h = h0 + i;
        float vals[8];
        #pragma unroll
        for (int j = 0; j < 8; j++) {
            vals[j] = acc[i][j];
            if (ISH && (g0 + j == h)) vals[j] = neg_inf_f();
        }
        float4 r0 = {vals[0], vals[1], vals[2], vals[3]};
        float4 r1 = {vals[4], vals[5], vals[6], vals[7]};
        *reinterpret_cast<float4*>(O + h * 128 + g0)     = r0;
        *reinterpret_cast<float4*>(O + h * 128 + g0 + 4) = r1;
    }
}

// ---------------------------------------------------------------------------
// Kernel 4: joint softmax over 256 concat scores, one warp per pixel, in place.
// grid: B*H*W/8 blocks of 256 threads (8 warps).
// ---------------------------------------------------------------------------
__global__ __launch_bounds__(256) void softmax_kernel()
{
    const int wid  = blockIdx.x * 8 + (threadIdx.x >> 5);
    const int lane = threadIdx.x & 31;
    const int b  = wid >> 14;
    const int hw = wid & 16383;
    const int h  = hw >> 7, w = hw & 127;

    float* pH = g_eH + ((size_t)(b * Wn + w) * Hh + h) * Hh;
    float* pW = g_eW + ((size_t)(b * Hh + h) * Wn + w) * Wn;

    float4 vh = *reinterpret_cast<float4*>(pH + lane * 4);
    float4 vw = *reinterpret_cast<float4*>(pW + lane * 4);

    float m = fmaxf(fmaxf(fmaxf(vh.x, vh.y), fmaxf(vh.z, vh.w)),
                    fmaxf(fmaxf(vw.x, vw.y), fmaxf(vw.z, vw.w)));
    #pragma unroll
    for (int off = 16; off; off >>= 1)
        m = fmaxf(m, __shfl_xor_sync(0xffffffffu, m, off));

    vh.x = __expf(vh.x - m); vh.y = __expf(vh.y - m);
    vh.z = __expf(vh.z - m); vh.w = __expf(vh.w - m);
    vw.x = __expf(vw.x - m); vw.y = __expf(vw.y - m);
    vw.z = __expf(vw.z - m); vw.w = __expf(vw.w - m);

    float s = vh.x + vh.y + vh.z + vh.w + vw.x + vw.y + vw.z + vw.w;
    #pragma unroll
    for (int off = 16; off; off >>= 1)
        s += __shfl_xor_sync(0xffffffffu, s, off);

    const float inv = 1.f / s;
    vh.x *= inv; vh.y *= inv; vh.z *= inv; vh.w *= inv;
    vw.x *= inv; vw.y *= inv; vw.z *= inv; vw.w *= inv;

    *reinterpret_cast<float4*>(pH + lane * 4) = vh;
    *reinterpret_cast<float4*>(pW + lane * 4) = vw;
}

// ---------------------------------------------------------------------------
// Kernel 5/6: output GEMMs, 128x128x128 per block.
// ISH=true : per (b,w): oH[h][c] = sum_g aH[h][g] * v_whc[g][c]
// ISH=false: per (b,h): oW[w][c] = sum_g aW[w][g] * v_hwc[g][c]
// grid: (2 c-halves, B*128), block 256, 8x8 per thread.
// ---------------------------------------------------------------------------
template <bool ISH>
__global__ __launch_bounds__(256) void out_kernel()
{
    __shared__ float As[16][132];   // As[g][h], padded
    __shared__ float Bs[16][132];   // Bs[g][c], padded

    const int bs = blockIdx.y;
    const int c0 = blockIdx.x * 128;
    const int t  = threadIdx.x;
    const float* A = (ISH ? g_eH   : g_eW)   + (size_t)bs * 128 * 128;
    const float* V = (ISH ? g_v_whc : g_v_hwc) + (size_t)bs * 128 * Cc;
    float* O       = (ISH ? g_oH   : g_oW)   + (size_t)bs * 128 * Cc;

    const int tx = t & 15, ty = t >> 4;
    const int h0 = ty * 8, cc0 = tx * 8;

    float acc[8][8];
    #pragma unroll
    for (int i = 0; i < 8; i++)
        #pragma unroll
        for (int j = 0; j < 8; j++) acc[i][j] = 0.f;

    for (int kc = 0; kc < 128; kc += 16) {
        float4 a4[2], b4[2];
        #pragma unroll
        for (int q = 0; q < 2; q++) {
            const int idx = q * 256 + t;        // 0..511
            const int ha  = idx >> 2;           // 0..127
            const int gq  = (idx & 3) * 4;      // 0,4,8,12
            a4[q] = *reinterpret_cast<const float4*>(A + ha * 128 + kc + gq);
            const int kk = idx >> 5;            // 0..15
            const int cq = (idx & 31) * 4;      // 0..124
            b4[q] = *reinterpret_cast<const float4*>(V + (size_t)(kc + kk) * Cc + c0 + cq);
        }
        __syncthreads();
        #pragma unroll
        for (int q = 0; q < 2; q++) {
            const int idx = q * 256 + t;
            const int ha  = idx >> 2;
            const int gq  = (idx & 3) * 4;
            As[gq + 0][ha] = a4[q].x;
            As[gq + 1][ha] = a4[q].y;
            As[gq + 2][ha] = a4[q].z;
            As[gq + 3][ha] = a4[q].w;
            const int kk = idx >> 5;
            const int cq = (idx & 31) * 4;
            *reinterpret_cast<float4*>(&Bs[kk][cq]) = b4[q];
        }
        __syncthreads();
        #pragma unroll
        for (int kk = 0; kk < 16; kk++) {
            float4 av0 = *reinterpret_cast<float4*>(&As[kk][h0]);
            float4 av1 = *reinterpret_cast<float4*>(&As[kk][h0 + 4]);
            float4 bv0 = *reinterpret_cast<float4*>(&Bs[kk][cc0]);
            float4 bv1 = *reinterpret_cast<float4*>(&Bs[kk][cc0 + 4]);
            float a[8] = {av0.x, av0.y, av0.z, av0.w, av1.x, av1.y, av1.z, av1.w};
            float bb[8] = {bv0.x, bv0.y, bv0.z, bv0.w, bv1.x, bv1.y, bv1.z, bv1.w};
            #pragma unroll
            for (int i = 0; i < 8; i++)
                #pragma unroll
                for (int j = 0; j < 8; j++)
                    acc[i][j] += a[i] * bb[j];
        }
        __syncthreads();
    }

    #pragma unroll
    for (int i = 0; i < 8; i++) {
        float* row = O + (size_t)(h0 + i) * Cc + c0 + cc0;
        float4 r0 = {acc[i][0], acc[i][1], acc[i][2], acc[i][3]};
        float4 r1 = {acc[i][4], acc[i][5], acc[i][6], acc[i][7]};
        *reinterpret_cast<float4*>(row)     = r0;
        *reinterpret_cast<float4*>(row + 4) = r1;
    }
}

// ---------------------------------------------------------------------------
// Kernel 7: out[b,c,h,w] = gamma*(oH[b,w,h,c] + oW[b,h,w,c]) + x[b,c,h,w].
// grid: (W/32, C/32, B*H), block 256; smem 32x32 transpose.
// ---------------------------------------------------------------------------
__global__ __launch_bounds__(256) void final_kernel(
    const float* __restrict__ x, const float* __restrict__ gamma,
    float* __restrict__ out)
{
    __shared__ float sm[32][33];
    const int bh = blockIdx.z;
    const int b = bh >> 7, h = bh & 127;
    const int c0 = blockIdx.y * 32;
    const int w0 = blockIdx.x * 32;
    const int t  = threadIdx.x;
    const float g = gamma[0];

    {
        const int wr = t >> 3;
        const int cq = (t & 7) * 4;
        const float4 a = *reinterpret_cast<const float4*>(
            g_oH + ((size_t)(b * Wn + (w0 + wr)) * Hh + h) * Cc + c0 + cq);
        const float4 bb = *reinterpret_cast<const float4*>(
            g_oW + ((size_t)(b * Hh + h) * Wn + (w0 + wr)) * Cc + c0 + cq);
        sm[wr][cq + 0] = a.x + bb.x;
        sm[wr][cq + 1] = a.y + bb.y;
        sm[wr][cq + 2] = a.z + bb.z;
        sm[wr][cq + 3] = a.w + bb.w;
    }
    __syncthreads();
    {
        const int cr = t >> 3;
        const int wq = (t & 7) * 4;
        const size_t oidx = ((size_t)(b * Cc + c0 + cr) * Hh + h) * Wn + w0 + wq;
        const float4 xr = *reinterpret_cast<const float4*>(x + oidx);
        float4 r;
        r.x = g * sm[wq + 0][cr] + xr.x;
        r.y = g * sm[wq + 1][cr] + xr.y;
        r.z = g * sm[wq + 2][cr] + xr.z;
        r.w = g * sm[wq + 3][cr] + xr.w;
        *reinterpret_cast<float4*>(out + oidx) = r;
    }
}

// ---------------------------------------------------------------------------
extern "C" void kernel_launch(void* const* d_in, const int* in_sizes, int n_in,
                              void* d_out, int out_size)
{
    const float* x     = (const float*)d_in[0];
    const float* Wq    = (const float*)d_in[1];
    const float* bq    = (const float*)d_in[2];
    const float* Wk    = (const float*)d_in[3];
    const float* bk    = (const float*)d_in[4];
    const float* Wv    = (const float*)d_in[5];
    const float* bv    = (const float*)d_in[6];
    const float* gamma = (const float*)d_in[7];
    float* out = (float*)d_out;

    proj_kernel<<<dim3(HWn / 64, 5, Bn), 256>>>(x, Wq, bq, Wk, bk, Wv, bv);

    score_kernel<true ><<<Bn * Wn, 256>>>();
    score_kernel<false><<<Bn * Hh, 256>>>();

    softmax_kernel<<<(Bn * HWn) / 8, 256>>>();

    out_kernel<true ><<<dim3(2, Bn * Wn), 256>>>();
    out_kernel<false><<<dim3(2, Bn * Hh), 256>>>();

    final_kernel<<<dim3(Wn / 32, Cc / 32, Bn * Hh), 256>>>(x, gamma, out);
}

// round 6
// speedup vs baseline: 1.7875x; 1.7875x over previous
#include <cuda_runtime.h>
#include <cuda_bf16.h>
#include <cstdint>

#define Bn 8
#define Cc 256
#define CQn 32
#define Hh 128
#define Wn 128
#define HWn (Hh*Wn)

__device__ __nv_bfloat16 g_Wh[320*256], g_Wl[320*256];   // split W rows: [q32;k32;v256]
__device__ float g_bs[320];
__device__ __nv_bfloat16 g_xh[(size_t)Bn*HWn*Cc], g_xl[(size_t)Bn*HWn*Cc]; // [b][p][c]
__device__ float g_q_hw[(size_t)Bn*HWn*CQn], g_q_wh[(size_t)Bn*HWn*CQn];
__device__ float g_k_hw[(size_t)Bn*HWn*CQn], g_k_wh[(size_t)Bn*HWn*CQn];
__device__ float g_va[(size_t)Bn*Cc*HWn];   // [b][c][h][w]
__device__ float g_vb[(size_t)Bn*Cc*HWn];   // [b][c][w][h]
__device__ float g_eH[(size_t)Bn*Wn*Hh*Hh]; // [b][w][h][g]
__device__ float g_eW[(size_t)Bn*Hh*Wn*Wn]; // [b][h][w][g]
__device__ float g_oH[(size_t)Bn*HWn*Cc];   // [b][w][h][c]
__device__ float g_oW[(size_t)Bn*HWn*Cc];   // [b][h][w][c]

__device__ __forceinline__ float neg_inf_f() { return __int_as_float(0xff800000); }
__device__ __forceinline__ float tf32r(float f) {
    uint32_t u; asm("cvt.rna.tf32.f32 %0, %1;" : "=r"(u) : "f"(f));
    return __uint_as_float(u);
}
// bf16 split-MMA: D += A16x16 * B16x8 (bf16, f32 accum)
__device__ __forceinline__ void mma16(float* d, uint32_t a0, uint32_t a1, uint32_t a2,
                                      uint32_t a3, uint32_t b0, uint32_t b1) {
    asm volatile("mma.sync.aligned.m16n8k16.row.col.f32.bf16.bf16.f32 "
                 "{%0,%1,%2,%3},{%4,%5,%6,%7},{%8,%9},{%0,%1,%2,%3};"
                 : "+f"(d[0]), "+f"(d[1]), "+f"(d[2]), "+f"(d[3])
                 : "r"(a0), "r"(a1), "r"(a2), "r"(a3), "r"(b0), "r"(b1));
}
// tf32 MMA: D += A16x8 * B8x8
__device__ __forceinline__ void mma8(float* d, const float* a, const float* b) {
    asm volatile("mma.sync.aligned.m16n8k8.row.col.f32.tf32.tf32.f32 "
                 "{%0,%1,%2,%3},{%4,%5,%6,%7},{%8,%9},{%0,%1,%2,%3};"
                 : "+f"(d[0]), "+f"(d[1]), "+f"(d[2]), "+f"(d[3])
                 : "r"(__float_as_uint(a[0])), "r"(__float_as_uint(a[1])),
                   "r"(__float_as_uint(a[2])), "r"(__float_as_uint(a[3])),
                   "r"(__float_as_uint(b[0])), "r"(__float_as_uint(b[1])));
}

// prep: split W rows [Wq;Wk;Wv] into bf16 hi/lo planes. grid 320, block 256.
__global__ __launch_bounds__(256) void prep_kernel(
    const float* __restrict__ Wq, const float* __restrict__ bq,
    const float* __restrict__ Wk, const float* __restrict__ bk,
    const float* __restrict__ Wv, const float* __restrict__ bv)
{
    const int r = blockIdx.x, t = threadIdx.x;
    const float* src; const float* bsrc; int o;
    if (r < 32)      { src = Wq; bsrc = bq; o = r; }
    else if (r < 64) { src = Wk; bsrc = bk; o = r - 32; }
    else             { src = Wv; bsrc = bv; o = r - 64; }
    float v = src[o*256 + t];
    __nv_bfloat16 h = __float2bfloat16(v);
    g_Wh[r*256 + t] = h;
    g_Wl[r*256 + t] = __float2bfloat16(v - __bfloat162float(h));
    if (t == 0) g_bs[r] = bsrc[o];
}

// xt: x[b][c][p] -> split bf16 [b][p][c]. grid (512,8,8), block 256.
__global__ __launch_bounds__(256) void xt_kernel(const float* __restrict__ x)
{
    __shared__ float tl[32][33];
    const int b = blockIdx.z, c0 = blockIdx.y*32, p0 = blockIdx.x*32;
    const int tx = threadIdx.x & 31, ty = threadIdx.x >> 5;
    #pragma unroll
    for (int i = 0; i < 4; i++) {
        int c = ty + i*8;
        tl[c][tx] = x[((size_t)(b*Cc + c0 + c))*HWn + p0 + tx];
    }
    __syncthreads();
    #pragma unroll
    for (int i = 0; i < 4; i++) {
        int p = ty + i*8;
        float v = tl[tx][p];
        __nv_bfloat16 h = __float2bfloat16(v);
        size_t idx = ((size_t)b*HWn + p0 + p)*Cc + c0 + tx;
        g_xh[idx] = h;
        g_xl[idx] = __float2bfloat16(v - __bfloat162float(h));
    }
}

// proj: per (b, h, mt): D[128 pixels x 64 oc] = x(128x256) @ W_mt^T, bf16 3-pass.
// 8 warps 4m x 2n; warp tile 32x32. grid (128, 5, 8), block 256.
__global__ __launch_bounds__(256) void proj_mma()
{
    __shared__ __align__(16) uint32_t pool[8448];  // AHI@0 ALO@2560 BHI@5120 BLO@6400 (stride 20w)
    __shared__ float s_bias[64];
    const int t = threadIdx.x, wid = t >> 5, lane = t & 31;
    const int g8 = lane >> 2, tig = lane & 3;
    const int warp_m = wid & 3, warp_n = wid >> 2;
    const int h = blockIdx.x, mt = blockIdx.y, b = blockIdx.z;
    const int px0 = h * 128;
    if (t < 64) s_bias[t] = g_bs[mt*64 + t];

    const __nv_bfloat16* Xh = g_xh + ((size_t)b*HWn + px0)*Cc;
    const __nv_bfloat16* Xl = g_xl + ((size_t)b*HWn + px0)*Cc;
    const __nv_bfloat16* Wh = g_Wh + (size_t)mt*64*Cc;
    const __nv_bfloat16* Wl = g_Wl + (size_t)mt*64*Cc;

    float acc[2][4][4] = {};
    const int ar = t >> 1, aw = (t & 1)*8;   // A row, word offset
    const int br = t >> 2, bw = (t & 3)*4;   // B row, word offset

    for (int kc = 0; kc < 8; kc++) {
        const size_t ae = (size_t)ar*Cc + kc*32 + aw*2;
        const size_t be = (size_t)br*Cc + kc*32 + bw*2;
        uint4 ah0 = *(const uint4*)(Xh + ae), ah1 = *(const uint4*)(Xh + ae + 8);
        uint4 al0 = *(const uint4*)(Xl + ae), al1 = *(const uint4*)(Xl + ae + 8);
        uint4 bh  = *(const uint4*)(Wh + be), bl  = *(const uint4*)(Wl + be);
        __syncthreads();
        *(uint4*)&pool[ar*20 + aw]          = ah0;
        *(uint4*)&pool[ar*20 + aw + 4]      = ah1;
        *(uint4*)&pool[2560 + ar*20 + aw]   = al0;
        *(uint4*)&pool[2560 + ar*20 + aw+4] = al1;
        *(uint4*)&pool[5120 + br*20 + bw]   = bh;
        *(uint4*)&pool[6400 + br*20 + bw]   = bl;
        __syncthreads();
        #pragma unroll
        for (int ks = 0; ks < 2; ks++) {
            const int kw = ks*8;
            uint32_t ahf[2][4], alf[2][4];
            #pragma unroll
            for (int mi = 0; mi < 2; mi++) {
                const int m0 = warp_m*32 + mi*16;
                ahf[mi][0] = pool[(m0+g8  )*20 + kw + tig];
                ahf[mi][1] = pool[(m0+g8+8)*20 + kw + tig];
                ahf[mi][2] = pool[(m0+g8  )*20 + kw + tig + 4];
                ahf[mi][3] = pool[(m0+g8+8)*20 + kw + tig + 4];
                alf[mi][0] = pool[2560 + (m0+g8  )*20 + kw + tig];
                alf[mi][1] = pool[2560 + (m0+g8+8)*20 + kw + tig];
                alf[mi][2] = pool[2560 + (m0+g8  )*20 + kw + tig + 4];
                alf[mi][3] = pool[2560 + (m0+g8+8)*20 + kw + tig + 4];
            }
            #pragma unroll
            for (int ni = 0; ni < 4; ni++) {
                const int n = warp_n*32 + ni*8 + g8;
                uint32_t bh0 = pool[5120 + n*20 + kw + tig];
                uint32_t bh1 = pool[5120 + n*20 + kw + tig + 4];
                uint32_t bl0 = pool[6400 + n*20 + kw + tig];
                uint32_t bl1 = pool[6400 + n*20 + kw + tig + 4];
                #pragma unroll
                for (int mi = 0; mi < 2; mi++) {
                    mma16(acc[mi][ni], ahf[mi][0], ahf[mi][1], ahf[mi][2], ahf[mi][3], bh0, bh1);
                    mma16(acc[mi][ni], ahf[mi][0], ahf[mi][1], ahf[mi][2], ahf[mi][3], bl0, bl1);
                    mma16(acc[mi][ni], alf[mi][0], alf[mi][1], alf[mi][2], alf[mi][3], bh0, bh1);
                }
            }
        }
    }

    if (mt == 0) {
        // q (cols 0-31) / k (cols 32-63): direct dual-layout float2 stores.
        #pragma unroll
        for (int mi = 0; mi < 2; mi++)
            #pragma unroll
            for (int ni = 0; ni < 4; ni++) {
                const int n = warp_n*32 + ni*8 + tig*2;
                const float b0 = s_bias[n], b1 = s_bias[n+1];
                float* hwp = (n < 32 ? g_q_hw : g_k_hw);
                float* whp = (n < 32 ? g_q_wh : g_k_wh);
                const int o = n & 31;
                #pragma unroll
                for (int hf = 0; hf < 2; hf++) {
                    const int w = warp_m*32 + mi*16 + g8 + hf*8;
                    float2 v = {acc[mi][ni][hf*2] + b0, acc[mi][ni][hf*2+1] + b1};
                    *(float2*)(hwp + ((size_t)(b*Hh + h)*Wn + w)*CQn + o) = v;
                    *(float2*)(whp + ((size_t)(b*Wn + w)*Hh + h)*CQn + o) = v;
                }
            }
    } else {
        // v: transpose via smem -> g_va[b][c][h][w], coalesced float4.
        float* tb = (float*)pool;   // [64 c][132 pixels]
        __syncthreads();
        #pragma unroll
        for (int mi = 0; mi < 2; mi++)
            #pragma unroll
            for (int ni = 0; ni < 4; ni++) {
                const int n = warp_n*32 + ni*8 + tig*2;
                const float b0 = s_bias[n], b1 = s_bias[n+1];
                #pragma unroll
                for (int hf = 0; hf < 2; hf++) {
                    const int w = warp_m*32 + mi*16 + g8 + hf*8;
                    tb[n*132 + w]     = acc[mi][ni][hf*2]   + b0;
                    tb[(n+1)*132 + w] = acc[mi][ni][hf*2+1] + b1;
                }
            }
        __syncthreads();
        const int c = t >> 2, p4 = (t & 3)*32;
        float* dst = g_va + ((size_t)(b*Cc + (mt-1)*64 + c))*HWn + px0 + p4;
        #pragma unroll
        for (int i = 0; i < 32; i += 4)
            *(float4*)(dst + i) = *(float4*)&tb[c*132 + p4 + i];
    }
}

// vb: g_va[b][c][h][w] -> g_vb[b][c][w][h]. grid (4,4,2048), block 256.
__global__ __launch_bounds__(256) void vb_kernel()
{
    __shared__ float tl[32][33];
    const int bc = blockIdx.z, w0 = blockIdx.x*32, h0 = blockIdx.y*32;
    const int tx = threadIdx.x & 31, ty = threadIdx.x >> 5;
    #pragma unroll
    for (int i = 0; i < 4; i++)
        tl[ty + i*8][tx] = g_va[((size_t)bc*Hh + h0 + ty + i*8)*Wn + w0 + tx];
    __syncthreads();
    #pragma unroll
    for (int i = 0; i < 4; i++)
        g_vb[((size_t)bc*Wn + w0 + ty + i*8)*Hh + h0 + tx] = tl[tx][ty + i*8];
}

// score<ISH>: 128x128x32 fp32. grid B*128, block 256.
template <bool ISH>
__global__ __launch_bounds__(256) void score_kernel()
{
    __shared__ float Qs[128][32];
    __shared__ float Ks[32][132];
    const int bs = blockIdx.x, t = threadIdx.x;
    const float* Q = (ISH ? g_q_wh : g_q_hw) + (size_t)bs * 128 * CQn;
    const float* K = (ISH ? g_k_wh : g_k_hw) + (size_t)bs * 128 * CQn;
    float* O       = (ISH ? g_eH   : g_eW)   + (size_t)bs * 128 * 128;

    #pragma unroll
    for (int q = 0; q < 4; q++) {
        const int idx = q*256 + t, row = idx >> 3, oq = (idx & 7)*4;
        *(float4*)&Qs[row][oq] = *(const float4*)(Q + row*CQn + oq);
        float4 kv = *(const float4*)(K + row*CQn + oq);
        Ks[oq+0][row] = kv.x; Ks[oq+1][row] = kv.y;
        Ks[oq+2][row] = kv.z; Ks[oq+3][row] = kv.w;
    }
    __syncthreads();

    const int tx = t & 15, ty = t >> 4, h0 = ty*8, g0 = tx*8;
    float acc[8][8] = {};
    #pragma unroll
    for (int o = 0; o < 32; o++) {
        float a[8];
        #pragma unroll
        for (int i = 0; i < 8; i++) a[i] = Qs[h0+i][o];
        float4 b0 = *(float4*)&Ks[o][g0], b1 = *(float4*)&Ks[o][g0+4];
        float bb[8] = {b0.x,b0.y,b0.z,b0.w,b1.x,b1.y,b1.z,b1.w};
        #pragma unroll
        for (int i = 0; i < 8; i++)
            #pragma unroll
            for (int j = 0; j < 8; j++) acc[i][j] += a[i]*bb[j];
    }
    #pragma unroll
    for (int i = 0; i < 8; i++) {
        const int hh = h0 + i;
        float v[8];
        #pragma unroll
        for (int j = 0; j < 8; j++) {
            v[j] = acc[i][j];
            if (ISH && (g0 + j == hh)) v[j] = neg_inf_f();
        }
        *(float4*)(O + hh*128 + g0)     = make_float4(v[0],v[1],v[2],v[3]);
        *(float4*)(O + hh*128 + g0 + 4) = make_float4(v[4],v[5],v[6],v[7]);
    }
}

// softmax: joint 256-way per pixel, in place. grid 16384, block 256.
__global__ __launch_bounds__(256) void softmax_kernel()
{
    const int wid = blockIdx.x*8 + (threadIdx.x >> 5), lane = threadIdx.x & 31;
    const int b = wid >> 14, hw = wid & 16383, h = hw >> 7, w = hw & 127;
    float* pH = g_eH + ((size_t)(b*Wn + w)*Hh + h)*Hh;
    float* pW = g_eW + ((size_t)(b*Hh + h)*Wn + w)*Wn;
    float4 vh = *(float4*)(pH + lane*4);
    float4 vw = *(float4*)(pW + lane*4);
    float m = fmaxf(fmaxf(fmaxf(vh.x,vh.y),fmaxf(vh.z,vh.w)),
                    fmaxf(fmaxf(vw.x,vw.y),fmaxf(vw.z,vw.w)));
    #pragma unroll
    for (int off = 16; off; off >>= 1) m = fmaxf(m, __shfl_xor_sync(~0u, m, off));
    vh.x=__expf(vh.x-m); vh.y=__expf(vh.y-m); vh.z=__expf(vh.z-m); vh.w=__expf(vh.w-m);
    vw.x=__expf(vw.x-m); vw.y=__expf(vw.y-m); vw.z=__expf(vw.z-m); vw.w=__expf(vw.w-m);
    float s = vh.x+vh.y+vh.z+vh.w+vw.x+vw.y+vw.z+vw.w;
    #pragma unroll
    for (int off = 16; off; off >>= 1) s += __shfl_xor_sync(~0u, s, off);
    const float inv = 1.f/s;
    vh.x*=inv; vh.y*=inv; vh.z*=inv; vh.w*=inv;
    vw.x*=inv; vw.y*=inv; vw.z*=inv; vw.w*=inv;
    *(float4*)(pH + lane*4) = vh;
    *(float4*)(pW + lane*4) = vw;
}

// out<ISH>: per (b,s,chalf): D[128 spatial x 128 c] = att @ v^T, tf32 1-pass.
// A[m][k]=att rows; B[c][k]=v channel rows (k contiguous). grid (2,1024), block 256.
template <bool ISH>
__global__ __launch_bounds__(256) void out_mma()
{
    __shared__ __align__(16) float As2[128][36];
    __shared__ __align__(16) float Bs2[128][36];
    const int t = threadIdx.x, wid = t >> 5, lane = t & 31;
    const int g8 = lane >> 2, tig = lane & 3;
    const int warp_m = wid & 3, warp_n = wid >> 2;
    const int bs = blockIdx.y, b = bs >> 7, s = bs & 127;
    const int c0 = blockIdx.x * 128;
    const float* A = (ISH ? g_eH : g_eW) + (size_t)bs*16384;
    const float* V = (ISH ? g_vb : g_va) + (size_t)b*Cc*HWn + (size_t)s*Wn;
    float* O       = (ISH ? g_oH : g_oW) + (size_t)bs*128*Cc;

    float acc[2][8][4] = {};
    const int ar = t >> 1, akq = (t & 1)*16;

    for (int kc = 0; kc < 4; kc++) {
        float4 av[4], bv[4];
        #pragma unroll
        for (int i = 0; i < 4; i++) {
            av[i] = *(const float4*)(A + (size_t)ar*128 + kc*32 + akq + i*4);
            bv[i] = *(const float4*)(V + (size_t)(c0 + ar)*HWn + kc*32 + akq + i*4);
        }
        __syncthreads();
        #pragma unroll
        for (int i = 0; i < 4; i++) {
            As2[ar][akq+i*4+0] = tf32r(av[i].x); As2[ar][akq+i*4+1] = tf32r(av[i].y);
            As2[ar][akq+i*4+2] = tf32r(av[i].z); As2[ar][akq+i*4+3] = tf32r(av[i].w);
            Bs2[ar][akq+i*4+0] = tf32r(bv[i].x); Bs2[ar][akq+i*4+1] = tf32r(bv[i].y);
            Bs2[ar][akq+i*4+2] = tf32r(bv[i].z); Bs2[ar][akq+i*4+3] = tf32r(bv[i].w);
        }
        __syncthreads();
        #pragma unroll
        for (int kk = 0; kk < 4; kk++) {
            const int k0 = kk*8;
            float a[2][4];
            #pragma unroll
            for (int mi = 0; mi < 2; mi++) {
                const int m0 = warp_m*32 + mi*16;
                a[mi][0] = As2[m0+g8  ][k0+tig];
                a[mi][1] = As2[m0+g8+8][k0+tig];
                a[mi][2] = As2[m0+g8  ][k0+tig+4];
                a[mi][3] = As2[m0+g8+8][k0+tig+4];
            }
            #pragma unroll
            for (int ni = 0; ni < 8; ni++) {
                const int nn = warp_n*64 + ni*8 + g8;
                float bf[2] = {Bs2[nn][k0+tig], Bs2[nn][k0+tig+4]};
                #pragma unroll
                for (int mi = 0; mi < 2; mi++) mma8(acc[mi][ni], a[mi], bf);
            }
        }
    }
    #pragma unroll
    for (int mi = 0; mi < 2; mi++)
        #pragma unroll
        for (int ni = 0; ni < 8; ni++) {
            const int m = warp_m*32 + mi*16 + g8;
            const int n = c0 + warp_n*64 + ni*8 + tig*2;
            *(float2*)(O + (size_t)m*Cc + n)     = make_float2(acc[mi][ni][0], acc[mi][ni][1]);
            *(float2*)(O + (size_t)(m+8)*Cc + n) = make_float2(acc[mi][ni][2], acc[mi][ni][3]);
        }
}

// final: out = gamma*(oH + oW) + x (NCHW). grid (4,8,1024), block 256.
__global__ __launch_bounds__(256) void final_kernel(
    const float* __restrict__ x, const float* __restrict__ gamma,
    float* __restrict__ out)
{
    __shared__ float sm[32][33];
    const int bh = blockIdx.z, b = bh >> 7, h = bh & 127;
    const int c0 = blockIdx.y*32, w0 = blockIdx.x*32;
    const int t = threadIdx.x;
    const float g = gamma[0];
    {
        const int wr = t >> 3, cq = (t & 7)*4;
        float4 a  = *(const float4*)(g_oH + ((size_t)(b*Wn + w0+wr)*Hh + h)*Cc + c0 + cq);
        float4 bb = *(const float4*)(g_oW + ((size_t)(b*Hh + h)*Wn + w0+wr)*Cc + c0 + cq);
        sm[wr][cq+0] = a.x + bb.x; sm[wr][cq+1] = a.y + bb.y;
        sm[wr][cq+2] = a.z + bb.z; sm[wr][cq+3] = a.w + bb.w;
    }
    __syncthreads();
    {
        const int cr = t >> 3, wq = (t & 7)*4;
        const size_t oidx = ((size_t)(b*Cc + c0 + cr)*Hh + h)*Wn + w0 + wq;
        float4 xr = *(const float4*)(x + oidx);
        float4 r;
        r.x = g*sm[wq+0][cr] + xr.x; r.y = g*sm[wq+1][cr] + xr.y;
        r.z = g*sm[wq+2][cr] + xr.z; r.w = g*sm[wq+3][cr] + xr.w;
        *(float4*)(out + oidx) = r;
    }
}

extern "C" void kernel_launch(void* const* d_in, const int* in_sizes, int n_in,
                              void* d_out, int out_size)
{
    const float* x     = (const float*)d_in[0];
    const float* Wq    = (const float*)d_in[1];
    const float* bq    = (const float*)d_in[2];
    const float* Wk    = (const float*)d_in[3];
    const float* bk    = (const float*)d_in[4];
    const float* Wv    = (const float*)d_in[5];
    const float* bv    = (const float*)d_in[6];
    const float* gamma = (const float*)d_in[7];
    float* out = (float*)d_out;

    prep_kernel<<<320, 256>>>(Wq, bq, Wk, bk, Wv, bv);
    xt_kernel<<<dim3(512, 8, 8), 256>>>(x);
    proj_mma<<<dim3(128, 5, 8), 256>>>();
    vb_kernel<<<dim3(4, 4, 2048), 256>>>();
    score_kernel<true ><<<1024, 256>>>();
    score_kernel<false><<<1024, 256>>>();
    softmax_kernel<<<16384, 256>>>();
    out_mma<true ><<<dim3(2, 1024), 256>>>();
    out_mma<false><<<dim3(2, 1024), 256>>>();
    final_kernel<<<dim3(4, 8, 1024), 256>>>(x, gamma, out);
}